// round 4
// baseline (speedup 1.0000x reference)
#include <cuda_runtime.h>
#include <cstddef>

// ---------------------------------------------------------------------------
// Problem constants
// ---------------------------------------------------------------------------
constexpr int B_   = 4;
constexpr int DIM  = 256;
constexpr int MID  = 128;
constexpr int HH   = 128;
constexpr int WW   = 128;

// ---------------------------------------------------------------------------
// Device scratch (no allocations allowed -> __device__ globals)
// ---------------------------------------------------------------------------
__device__ float g_p1[(size_t)B_ * MID * HH * WW];   // p1, then cp1, then s = cp1+cp2
__device__ float g_p2[(size_t)B_ * MID * HH * WW];   // p2
__device__ float g_t1[(size_t)B_ * DIM * HH * WW];   // bn1, then r (in-place)
__device__ float g_scale[1024];                      // p1:0 p2:128 c1:256 c2:512 p3:768
__device__ float g_bias[1024];

// ---------------------------------------------------------------------------
// BN folding: scale = g * rsqrt(v+eps); bias = b - m*scale
// ---------------------------------------------------------------------------
__global__ void bn_prep(const float* __restrict__ g, const float* __restrict__ b,
                        const float* __restrict__ m, const float* __restrict__ v,
                        float* __restrict__ scale, float* __restrict__ bias, int C)
{
    int i = blockIdx.x * blockDim.x + threadIdx.x;
    if (i < C) {
        float s = g[i] * rsqrtf(v[i] + 1e-5f);
        scale[i] = s;
        bias[i]  = b[i] - m[i] * s;
    }
}

// ---------------------------------------------------------------------------
// Fused conv + BN (+ optional elementwise add of another buffer) (+ ReLU).
//
// Block tile: 128 cout x (4 rows x 32 cols) pixels, 256 threads,
// per-thread microtile 8 cout x 8 pixels (64 fp32 accumulators).
// K loop chunked over CC input channels through shared memory.
//
// Weight smem layout [co][ci*KS*KS + k]: inner-loop reads are warp broadcasts
// (2 distinct addresses/warp) -> conflict free; gmem weight loads are
// contiguous float4 runs per cout.
// ---------------------------------------------------------------------------
template<int CIN, int KS, int CC, bool RELU, bool ADD>
__global__ __launch_bounds__(256, 2)
void conv_bn(const float* __restrict__ in, const float* __restrict__ wgt,
             const float* __restrict__ scale, const float* __restrict__ bias,
             const float* __restrict__ addsrc, float* __restrict__ out, int COUT)
{
    constexpr int TH2   = 4;
    constexpr int TW2   = 32;
    constexpr int BC    = 128;
    constexpr int PAD   = (KS - 1) / 2;
    constexpr int XROWS = TH2 + KS - 1;
    constexpr int SXW   = 36;               // padded row width (16B aligned, odd 16B stride)
    constexpr int WN    = CC * KS * KS;     // weight floats per cout per chunk
    constexpr int W4    = WN / 4;

    __shared__ float sx[CC * XROWS * SXW];
    __shared__ float sw[BC * WN];

    const int tid  = threadIdx.x;
    const int tc   = tid >> 4;              // 0..15 cout group (couts tc*8 .. tc*8+7)
    const int pg   = tid & 15;              // pixel group
    const int prow = pg >> 2;               // 0..3
    const int pcol = (pg & 3) * 8;          // 0,8,16,24

    const int bx = blockIdx.x;
    const int b  = bx >> 7;                 // 128 pixel-tiles per image
    const int t  = bx & 127;
    const int h0 = (t >> 2) * TH2;          // 32 row-tiles
    const int w0 = (t & 3) * TW2;           // 4 col-tiles
    const int co0 = blockIdx.y * BC;

    float acc[8][8];
#pragma unroll
    for (int i = 0; i < 8; i++)
#pragma unroll
        for (int j = 0; j < 8; j++) acc[i][j] = 0.f;

    for (int ci0 = 0; ci0 < CIN; ci0 += CC) {
        __syncthreads();

        // ---- stage input patch: CC channels x XROWS x (TW2+KS-1), zero-padded ----
#pragma unroll 1
        for (int idx = tid; idx < CC * XROWS * SXW; idx += 256) {
            int cc  = idx % SXW;
            int t2  = idx / SXW;
            int rr  = t2 % XROWS;
            int ci  = t2 / XROWS;
            float val = 0.f;
            int gh = h0 - PAD + rr;
            int gw = w0 - PAD + cc;
            if (cc < TW2 + KS - 1 && (unsigned)gh < (unsigned)HH && (unsigned)gw < (unsigned)WW)
                val = in[(((size_t)b * CIN + ci0 + ci) * HH + gh) * WW + gw];
            sx[idx] = val;
        }

        // ---- stage weights: sw[co][t2], gmem contiguous per cout (float4) ----
        {
            const float4* wg4 = reinterpret_cast<const float4*>(wgt);
#pragma unroll 1
            for (int idx = tid; idx < BC * W4; idx += 256) {
                int co = idx / W4;
                int q  = idx % W4;
                float4 vv = wg4[(((size_t)(co0 + co) * CIN + ci0) * (KS * KS)) / 4 + q];
                reinterpret_cast<float4*>(&sw[co * WN])[q] = vv;
            }
        }
        __syncthreads();

        // ---- compute ----
#pragma unroll 1
        for (int ci = 0; ci < CC; ci++) {
#pragma unroll
            for (int r = 0; r < KS; r++) {
                float xin[8 + KS - 1];
                const float* xrow = &sx[(ci * XROWS + prow + r) * SXW + pcol];
#pragma unroll
                for (int j = 0; j < 8 + KS - 1; j++) xin[j] = xrow[j];
#pragma unroll
                for (int s = 0; s < KS; s++) {
                    const int k = ci * KS * KS + r * KS + s;
#pragma unroll
                    for (int i = 0; i < 8; i++) {
                        float wv = sw[(tc * 8 + i) * WN + k];
#pragma unroll
                        for (int j = 0; j < 8; j++)
                            acc[i][j] = fmaf(wv, xin[j + s], acc[i][j]);
                    }
                }
            }
        }
    }

    // ---- epilogue: BN (+add) (+relu), vectorized float4 stores ----
    const int hh = h0 + prow;
#pragma unroll
    for (int i = 0; i < 8; i++) {
        const int co = co0 + tc * 8 + i;
        const float sc = scale[co];
        const float bi = bias[co];
        const size_t base = (((size_t)b * COUT + co) * HH + hh) * WW + w0 + pcol;
#pragma unroll
        for (int j2 = 0; j2 < 2; j2++) {
            float4 o;
            o.x = acc[i][j2 * 4 + 0] * sc + bi;
            o.y = acc[i][j2 * 4 + 1] * sc + bi;
            o.z = acc[i][j2 * 4 + 2] * sc + bi;
            o.w = acc[i][j2 * 4 + 3] * sc + bi;
            if (ADD) {
                float4 ad = reinterpret_cast<const float4*>(addsrc + base)[j2];
                o.x += ad.x; o.y += ad.y; o.z += ad.z; o.w += ad.w;
            }
            if (RELU) {
                o.x = fmaxf(o.x, 0.f); o.y = fmaxf(o.y, 0.f);
                o.z = fmaxf(o.z, 0.f); o.w = fmaxf(o.w, 0.f);
            }
            reinterpret_cast<float4*>(out + base)[j2] = o;
        }
    }
}

// ---------------------------------------------------------------------------
// Corner pooling part 1: in-place reverse cummax over H on g_p1.
// One thread per (b, c, w) column; coalesced across w.
// ---------------------------------------------------------------------------
__global__ void colscan_kernel(float* __restrict__ p)
{
    int idx = blockIdx.x * blockDim.x + threadIdx.x;   // (b*MID + c)*WW + w
    if (idx >= B_ * MID * WW) return;
    int w  = idx % WW;
    int bc = idx / WW;
    float* col = p + (size_t)bc * HH * WW + w;
    float m = col[(HH - 1) * WW];
#pragma unroll 4
    for (int h = HH - 2; h >= 0; h--) {
        float v = col[h * WW];
        m = fmaxf(m, v);
        col[h * WW] = m;
    }
}

// ---------------------------------------------------------------------------
// Corner pooling part 2: reverse cummax over W of p2 (per row), added into s.
// One 128-thread block per (b, c, h) row; Hillis-Steele suffix-max in smem.
// ---------------------------------------------------------------------------
__global__ void rowscan_add_kernel(const float* __restrict__ p2, float* __restrict__ s)
{
    __shared__ float sm[WW];
    const int t = threadIdx.x;
    const size_t base = (size_t)blockIdx.x * WW;
    sm[t] = p2[base + t];
    __syncthreads();
#pragma unroll
    for (int off = 1; off < WW; off <<= 1) {
        float nv = sm[t];
        if (t + off < WW) nv = fmaxf(nv, sm[t + off]);
        __syncthreads();
        sm[t] = nv;
        __syncthreads();
    }
    s[base + t] += sm[t];
}

// ---------------------------------------------------------------------------
// Launch: p1, p2 -> corner pool -> bn1 -> bn2(+add,relu) -> p3
// ---------------------------------------------------------------------------
extern "C" void kernel_launch(void* const* d_in, const int* in_sizes, int n_in,
                              void* d_out, int out_size)
{
    (void)in_sizes; (void)n_in; (void)out_size;

    const float* x    = (const float*)d_in[0];
    const float* w_p1 = (const float*)d_in[1];
    const float* w_p2 = (const float*)d_in[6];
    const float* w_c1 = (const float*)d_in[11];
    const float* w_c2 = (const float*)d_in[16];
    const float* w_p3 = (const float*)d_in[21];

    float *p1, *p2, *t1, *sc, *bi;
    cudaGetSymbolAddress((void**)&p1, g_p1);
    cudaGetSymbolAddress((void**)&p2, g_p2);
    cudaGetSymbolAddress((void**)&t1, g_t1);
    cudaGetSymbolAddress((void**)&sc, g_scale);
    cudaGetSymbolAddress((void**)&bi, g_bias);

    // Fold all 5 batchnorms (offsets: p1=0, p2=128, c1=256, c2=512, p3=768)
    bn_prep<<<1, 256>>>((const float*)d_in[2],  (const float*)d_in[3],
                        (const float*)d_in[4],  (const float*)d_in[5],  sc + 0,   bi + 0,   MID);
    bn_prep<<<1, 256>>>((const float*)d_in[7],  (const float*)d_in[8],
                        (const float*)d_in[9],  (const float*)d_in[10], sc + 128, bi + 128, MID);
    bn_prep<<<1, 256>>>((const float*)d_in[12], (const float*)d_in[13],
                        (const float*)d_in[14], (const float*)d_in[15], sc + 256, bi + 256, DIM);
    bn_prep<<<1, 256>>>((const float*)d_in[17], (const float*)d_in[18],
                        (const float*)d_in[19], (const float*)d_in[20], sc + 512, bi + 512, DIM);
    bn_prep<<<1, 256>>>((const float*)d_in[22], (const float*)d_in[23],
                        (const float*)d_in[24], (const float*)d_in[25], sc + 768, bi + 768, DIM);

    const int PIX_TILES = B_ * (HH / 4) * (WW / 32);   // 512

    // p1 = relu(bn(conv3x3(x, w_p1)))   [256 -> 128]
    conv_bn<DIM, 3, 8, true, false><<<dim3(PIX_TILES, MID / 128), 256>>>(
        x, w_p1, sc + 0, bi + 0, nullptr, p1, MID);
    // p2 = relu(bn(conv3x3(x, w_p2)))   [256 -> 128]
    conv_bn<DIM, 3, 8, true, false><<<dim3(PIX_TILES, MID / 128), 256>>>(
        x, w_p2, sc + 128, bi + 128, nullptr, p2, MID);

    // corner pooling: p1 <- revcummax_H(p1); p1 += revcummax_W(p2)
    colscan_kernel<<<(B_ * MID * WW + 255) / 256, 256>>>(p1);
    rowscan_add_kernel<<<B_ * MID * HH, WW>>>(p2, p1);

    // t1 = bn(conv3x3(s, w_c1))  (no relu)   [128 -> 256]
    conv_bn<MID, 3, 8, false, false><<<dim3(PIX_TILES, DIM / 128), 256>>>(
        p1, w_c1, sc + 256, bi + 256, nullptr, t1, DIM);

    // t1 = relu(bn(conv1x1(x, w_c2)) + t1)   [256 -> 256], in-place add
    conv_bn<DIM, 1, 16, true, true><<<dim3(PIX_TILES, DIM / 128), 256>>>(
        x, w_c2, sc + 512, bi + 512, t1, t1, DIM);

    // out = relu(bn(conv3x3(r, w_p3)))       [256 -> 256]
    conv_bn<DIM, 3, 8, true, false><<<dim3(PIX_TILES, DIM / 128), 256>>>(
        t1, w_p3, sc + 768, bi + 768, nullptr, (float*)d_out, DIM);
}